// round 4
// baseline (speedup 1.0000x reference)
#include <cuda_runtime.h>
#include <cuda_bf16.h>
#include <math.h>
#include <cstdint>

#define BSZ 4
#define LSEQ 4096
#define DD 1024
#define CH 64
#define NCH (LSEQ / CH)
#define MROWS (BSZ * LSEQ)

// ---------------------------------------------------------------------------
// Scratch (device globals)
// ---------------------------------------------------------------------------
__device__ float2 g_u[(size_t)BSZ * LSEQ * DD];            // GEMM1 out (complex interleaved)
__device__ float2 g_last[BSZ * NCH * DD];
__device__ float2 g_cin[BSZ * NCH * DD];

__device__ __nv_bfloat16 g_inhi[(size_t)MROWS * DD];       // inputs hi/lo planes
__device__ __nv_bfloat16 g_inlo[(size_t)MROWS * DD];
__device__ __nv_bfloat16 g_wihi[(size_t)2 * DD * DD];      // Wi planes
__device__ __nv_bfloat16 g_wilo[(size_t)2 * DD * DD];
__device__ __nv_bfloat16 g_wohi[(size_t)DD * 2 * DD];      // Wo planes
__device__ __nv_bfloat16 g_wolo[(size_t)DD * 2 * DD];
__device__ __nv_bfloat16 g_xrhi[(size_t)MROWS * 2 * DD];   // GEMM2 A planes ([re|im])
__device__ __nv_bfloat16 g_xrlo[(size_t)MROWS * 2 * DD];

// ---------------------------------------------------------------------------
// helpers
// ---------------------------------------------------------------------------
__device__ __forceinline__ uint32_t smem_to_u32(const void* p) {
    uint32_t a;
    asm("{ .reg .u64 t; cvta.to.shared.u64 t, %1; cvt.u32.u64 %0, t; }" : "=r"(a) : "l"(p));
    return a;
}
#define SWZ128(o) ((o) ^ (((o) >> 3) & 0x70))
#define CP_ASYNC16(dst, src) \
    asm volatile("cp.async.cg.shared.global [%0], [%1], 16;" :: "r"(dst), "l"(src) : "memory")
#define CP_COMMIT() asm volatile("cp.async.commit_group;" ::: "memory")
#define CP_WAIT1()  asm volatile("cp.async.wait_group 1;" ::: "memory")

__device__ __forceinline__ void ldsm4(uint32_t* r, uint32_t a) {
    asm volatile("ldmatrix.sync.aligned.m8n8.x4.shared.b16 {%0,%1,%2,%3}, [%4];"
                 : "=r"(r[0]), "=r"(r[1]), "=r"(r[2]), "=r"(r[3]) : "r"(a));
}
__device__ __forceinline__ void ldsm2(uint32_t* r, uint32_t a) {
    asm volatile("ldmatrix.sync.aligned.m8n8.x2.shared.b16 {%0,%1}, [%2];"
                 : "=r"(r[0]), "=r"(r[1]) : "r"(a));
}
__device__ __forceinline__ void mma16816(float* c, const uint32_t* a, const uint32_t* b) {
    asm volatile(
        "mma.sync.aligned.m16n8k16.row.col.f32.bf16.bf16.f32 "
        "{%0,%1,%2,%3}, {%4,%5,%6,%7}, {%8,%9}, {%0,%1,%2,%3};"
        : "+f"(c[0]), "+f"(c[1]), "+f"(c[2]), "+f"(c[3])
        : "r"(a[0]), "r"(a[1]), "r"(a[2]), "r"(a[3]), "r"(b[0]), "r"(b[1]));
}

__device__ __forceinline__ void split1(float v, __nv_bfloat16& h, __nv_bfloat16& l) {
    h = __float2bfloat16(v);
    l = __float2bfloat16(v - __bfloat162float(h));
}

// ---------------------------------------------------------------------------
// Prepass: split fp32 -> hi/lo bf16 planes (vectorized float4 -> 2x uint2)
// ---------------------------------------------------------------------------
__global__ __launch_bounds__(256) void cvt_split(
    const float* __restrict__ src,
    __nv_bfloat16* __restrict__ hi,
    __nv_bfloat16* __restrict__ lo,
    int n4)
{
    int i = blockIdx.x * blockDim.x + threadIdx.x;
    if (i >= n4) return;
    float4 v = ((const float4*)src)[i];
    __nv_bfloat16 h[4], l[4];
    split1(v.x, h[0], l[0]);
    split1(v.y, h[1], l[1]);
    split1(v.z, h[2], l[2]);
    split1(v.w, h[3], l[3]);
    *(uint2*)(hi + (size_t)i * 4) = *(uint2*)h;
    *(uint2*)(lo + (size_t)i * 4) = *(uint2*)l;
}

// ---------------------------------------------------------------------------
// Split-bf16 HMMA GEMM with pre-split planes + cp.async 3-stage pipeline.
// C[M,N] = A[M,K] @ W[N,K]^T + bias (opt ReLU)
// CTA 128x128, BK=32 (fp32 k), 256 thr / 8 warps, warp tile 64x32.
// SMEM stage (32KB): A rows r: [hi 64B | lo 64B], then B same at +16KB.
// ---------------------------------------------------------------------------
static constexpr int STAGE_B = 32768;
static constexpr int NSTAGE  = 3;
static constexpr int SMEM_BYTES = NSTAGE * STAGE_B;   // 96 KB

template <bool RELU>
__global__ __launch_bounds__(256, 1) void gemm_mma(
    const __nv_bfloat16* __restrict__ Ahi,
    const __nv_bfloat16* __restrict__ Alo,
    const __nv_bfloat16* __restrict__ Bhi,
    const __nv_bfloat16* __restrict__ Blo,
    const float* __restrict__ bias,
    float* __restrict__ C,
    int N, int K)
{
    extern __shared__ __align__(1024) char smem[];
    const uint32_t sbase = smem_to_u32(smem);
    const int tid = threadIdx.x;
    const int lane = tid & 31, w = tid >> 5;
    const int m0 = blockIdx.y * 128, n0 = blockIdx.x * 128;
    const int mw = (w & 1) * 64;
    const int nw = (w >> 1) * 32;

    float acc[4][4][4];
#pragma unroll
    for (int i = 0; i < 4; i++)
#pragma unroll
        for (int j = 0; j < 4; j++)
#pragma unroll
            for (int r = 0; r < 4; r++) acc[i][j][r] = 0.0f;

    // loader: 1024 chunks of 16B per operand tile; 4 per thread per operand
    auto issue = [&](int kt, int s) {
        const uint32_t sA = sbase + s * STAGE_B;
#pragma unroll
        for (int p = 0; p < 4; p++) {
            const int c = tid + p * 256;
            const int row = c >> 3, sub = c & 7;
            const __nv_bfloat16* src =
                (sub < 4 ? Ahi : Alo) + (size_t)(m0 + row) * K + kt * 32 + (sub & 3) * 8;
            CP_ASYNC16(sA + SWZ128((uint32_t)(row * 128 + sub * 16)), src);
        }
#pragma unroll
        for (int p = 0; p < 4; p++) {
            const int c = tid + p * 256;
            const int row = c >> 3, sub = c & 7;
            const __nv_bfloat16* src =
                (sub < 4 ? Bhi : Blo) + (size_t)(n0 + row) * K + kt * 32 + (sub & 3) * 8;
            CP_ASYNC16(sA + 16384 + SWZ128((uint32_t)(row * 128 + sub * 16)), src);
        }
        CP_COMMIT();
    };

    auto compute = [&](int s) {
        const uint32_t aA = sbase + s * STAGE_B;
        const uint32_t aB = aA + 16384;
#pragma unroll
        for (int ks = 0; ks < 2; ks++) {
            uint32_t ah[4][4], al[4][4], bh[4][2], bl[4][2];
#pragma unroll
            for (int i = 0; i < 4; i++) {
                const int r = mw + i * 16 + (lane & 15);
                const uint32_t off = (uint32_t)(ks * 32 + ((lane >> 4) << 4));
                ldsm4(ah[i], aA + SWZ128((uint32_t)(r * 128) + off));
                ldsm4(al[i], aA + SWZ128((uint32_t)(r * 128) + off + 64));
            }
#pragma unroll
            for (int j = 0; j < 4; j++) {
                const int r = nw + j * 8 + (lane & 7);
                const uint32_t off = (uint32_t)(ks * 32 + ((lane >> 3) & 1) * 16);
                ldsm2(bh[j], aB + SWZ128((uint32_t)(r * 128) + off));
                ldsm2(bl[j], aB + SWZ128((uint32_t)(r * 128) + off + 64));
            }
#pragma unroll
            for (int i = 0; i < 4; i++)
#pragma unroll
                for (int j = 0; j < 4; j++) {
                    mma16816(acc[i][j], ah[i], bh[j]);
                    mma16816(acc[i][j], ah[i], bl[j]);
                    mma16816(acc[i][j], al[i], bh[j]);
                }
        }
    };

    const int NT = K / 32;
    issue(0, 0);
    issue(1, 1);

#pragma unroll 1
    for (int kt = 0; kt < NT; kt++) {
        const int s = kt % 3;
        CP_WAIT1();
        __syncthreads();
        if (kt + 2 < NT) issue(kt + 2, (kt + 2) % 3);
        compute(s);
    }

    // epilogue
#pragma unroll
    for (int i = 0; i < 4; i++) {
        const int mrow = m0 + mw + i * 16 + (lane >> 2);
#pragma unroll
        for (int j = 0; j < 4; j++) {
            const int ncol = n0 + nw + j * 8 + (lane & 3) * 2;
            const float b0 = bias[ncol], b1 = bias[ncol + 1];
            float2 v0 = make_float2(acc[i][j][0] + b0, acc[i][j][1] + b1);
            float2 v1 = make_float2(acc[i][j][2] + b0, acc[i][j][3] + b1);
            if (RELU) {
                v0.x = fmaxf(v0.x, 0.f); v0.y = fmaxf(v0.y, 0.f);
                v1.x = fmaxf(v1.x, 0.f); v1.y = fmaxf(v1.y, 0.f);
            }
            *(float2*)(C + (size_t)mrow * N + ncol) = v0;
            *(float2*)(C + (size_t)(mrow + 8) * N + ncol) = v1;
        }
    }
}

// ---------------------------------------------------------------------------
// Scan phase 1: local sequential scan within each chunk
// ---------------------------------------------------------------------------
__global__ __launch_bounds__(256) void scan_local(const float* __restrict__ plog)
{
    int t = blockIdx.x * blockDim.x + threadIdx.x;
    int d = t % DD;
    int c = (t / DD) % NCH;
    int b = t / (DD * NCH);

    float v  = expf(plog[d]);
    float th = expf(plog[DD + d]);
    float r  = expf(-v);
    float sn, cs;
    sincosf(th, &sn, &cs);
    float lre = r * cs, lim = r * sn;

    size_t base = ((size_t)(b * LSEQ + c * CH)) * DD + d;
    float2 s = make_float2(0.0f, 0.0f);
    float2 unext = g_u[base];
#pragma unroll 4
    for (int j = 0; j < CH; j++) {
        float2 u = unext;
        if (j + 1 < CH) unext = g_u[base + (size_t)(j + 1) * DD];
        float sre = fmaf(lre, s.x, fmaf(-lim, s.y, u.x));
        float sim = fmaf(lre, s.y, fmaf( lim, s.x, u.y));
        s = make_float2(sre, sim);
        g_u[base + (size_t)j * DD] = s;
    }
    g_last[(b * NCH + c) * DD + d] = s;
}

// ---------------------------------------------------------------------------
// Scan phase 2: carry scan across chunks
// ---------------------------------------------------------------------------
__global__ __launch_bounds__(256) void scan_carry(const float* __restrict__ plog)
{
    int t = blockIdx.x * blockDim.x + threadIdx.x;
    int d = t % DD;
    int b = t / DD;

    float v  = expf(plog[d]);
    float th = expf(plog[DD + d]);
    float Lr = expf(-(float)CH * v);
    float sn, cs;
    sincosf((float)CH * th, &sn, &cs);
    float Lre = Lr * cs, Lim = Lr * sn;

    float2 s = make_float2(0.0f, 0.0f);
    for (int k = 0; k < NCH; k++) {
        g_cin[(b * NCH + k) * DD + d] = s;
        float2 last = g_last[(b * NCH + k) * DD + d];
        float sre = fmaf(Lre, s.x, fmaf(-Lim, s.y, last.x));
        float sim = fmaf(Lre, s.y, fmaf( Lim, s.x, last.y));
        s = make_float2(sre, sim);
    }
}

// ---------------------------------------------------------------------------
// Scan phase 3: fixup + gamma, write GEMM2 A operand as hi/lo bf16 planes
// ---------------------------------------------------------------------------
__global__ __launch_bounds__(256) void scan_fix(const float* __restrict__ plog)
{
    int t = blockIdx.x * blockDim.x + threadIdx.x;
    int d = t % DD;
    int c = (t / DD) % NCH;
    int b = t / (DD * NCH);

    float v  = expf(plog[d]);
    float th = expf(plog[DD + d]);
    float g  = expf(plog[2 * DD + d]);
    float r  = expf(-v);
    float sn, cs;
    sincosf(th, &sn, &cs);
    float lre = r * cs, lim = r * sn;

    float2 cin = g_cin[(b * NCH + c) * DD + d];
    float pre = lre, pim = lim;

    size_t base = ((size_t)(b * LSEQ + c * CH)) * DD + d;
    size_t rbase = ((size_t)(b * LSEQ + c * CH)) * (2 * DD);

#pragma unroll 4
    for (int j = 0; j < CH; j++) {
        float2 x = g_u[base + (size_t)j * DD];
        float xre = g * (x.x + pre * cin.x - pim * cin.y);
        float xim = g * (x.y + pre * cin.y + pim * cin.x);
        __nv_bfloat16 h, l;
        size_t o0 = rbase + (size_t)j * (2 * DD) + d;
        size_t o1 = o0 + DD;
        split1(xre, h, l);
        g_xrhi[o0] = h; g_xrlo[o0] = l;
        split1(xim, h, l);
        g_xrhi[o1] = h; g_xrlo[o1] = l;
        float npre = pre * lre - pim * lim;
        pim = pre * lim + pim * lre;
        pre = npre;
    }
}

// ---------------------------------------------------------------------------
extern "C" void kernel_launch(void* const* d_in, const int* in_sizes, int n_in,
                              void* d_out, int out_size)
{
    const float* inputs = (const float*)d_in[0];
    const float* Wi     = (const float*)d_in[1];
    const float* bi     = (const float*)d_in[2];
    const float* Wo     = (const float*)d_in[3];
    const float* bo     = (const float*)d_in[4];
    const float* plog   = (const float*)d_in[5];

    void *up, *ih, *il, *wih, *wil, *woh, *wol, *xh, *xl;
    cudaGetSymbolAddress(&up,  g_u);
    cudaGetSymbolAddress(&ih,  g_inhi);  cudaGetSymbolAddress(&il,  g_inlo);
    cudaGetSymbolAddress(&wih, g_wihi);  cudaGetSymbolAddress(&wil, g_wilo);
    cudaGetSymbolAddress(&woh, g_wohi);  cudaGetSymbolAddress(&wol, g_wolo);
    cudaGetSymbolAddress(&xh,  g_xrhi);  cudaGetSymbolAddress(&xl,  g_xrlo);

    cudaFuncSetAttribute(gemm_mma<false>, cudaFuncAttributeMaxDynamicSharedMemorySize, SMEM_BYTES);
    cudaFuncSetAttribute(gemm_mma<true>,  cudaFuncAttributeMaxDynamicSharedMemorySize, SMEM_BYTES);

    // prepass: split fp32 -> bf16 hi/lo planes
    {
        int n4 = MROWS * DD / 4;
        cvt_split<<<(n4 + 255) / 256, 256>>>(inputs, (__nv_bfloat16*)ih, (__nv_bfloat16*)il, n4);
        n4 = 2 * DD * DD / 4;
        cvt_split<<<(n4 + 255) / 256, 256>>>(Wi, (__nv_bfloat16*)wih, (__nv_bfloat16*)wil, n4);
        cvt_split<<<(n4 + 255) / 256, 256>>>(Wo, (__nv_bfloat16*)woh, (__nv_bfloat16*)wol, n4);
    }

    // GEMM1: u = inputs @ Wi^T + bi  -> g_u
    gemm_mma<false><<<dim3((2 * DD) / 128, MROWS / 128), 256, SMEM_BYTES>>>(
        (const __nv_bfloat16*)ih, (const __nv_bfloat16*)il,
        (const __nv_bfloat16*)wih, (const __nv_bfloat16*)wil,
        bi, (float*)up, 2 * DD, DD);

    // Scan
    scan_local<<<(BSZ * NCH * DD) / 256, 256>>>(plog);
    scan_carry<<<(BSZ * DD) / 256, 256>>>(plog);
    scan_fix<<<(BSZ * NCH * DD) / 256, 256>>>(plog);

    // GEMM2: out = relu(xr @ Wo^T + bo)
    gemm_mma<true><<<dim3(DD / 128, MROWS / 128), 256, SMEM_BYTES>>>(
        (const __nv_bfloat16*)xh, (const __nv_bfloat16*)xl,
        (const __nv_bfloat16*)woh, (const __nv_bfloat16*)wol,
        bo, (float*)d_out, DD, 2 * DD);
}

// round 5
// speedup vs baseline: 1.5174x; 1.5174x over previous
#include <cuda_runtime.h>
#include <cuda_fp16.h>
#include <math.h>
#include <cstdint>

#define BSZ 4
#define LSEQ 4096
#define DD 1024
#define CH 64
#define NCH (LSEQ / CH)
#define MROWS (BSZ * LSEQ)

// ---------------------------------------------------------------------------
// Scratch (device globals)
// ---------------------------------------------------------------------------
__device__ float2 g_u[(size_t)BSZ * LSEQ * DD];        // GEMM1 out (complex interleaved)
__device__ float2 g_last[BSZ * NCH * DD];
__device__ float2 g_cin[BSZ * NCH * DD];

__device__ __half g_inh [(size_t)MROWS * DD];          // inputs, single fp16 plane
__device__ __half g_wihi[(size_t)2 * DD * DD];         // Wi hi/lo planes
__device__ __half g_wilo[(size_t)2 * DD * DD];
__device__ __half g_wohi[(size_t)DD * 2 * DD];         // Wo hi/lo planes
__device__ __half g_wolo[(size_t)DD * 2 * DD];
__device__ __half g_xrh [(size_t)MROWS * 2 * DD];      // GEMM2 A ([re|im]), single fp16 plane

// ---------------------------------------------------------------------------
// helpers
// ---------------------------------------------------------------------------
__device__ __forceinline__ uint32_t smem_to_u32(const void* p) {
    uint32_t a;
    asm("{ .reg .u64 t; cvta.to.shared.u64 t, %1; cvt.u32.u64 %0, t; }" : "=r"(a) : "l"(p));
    return a;
}
// 128B-row swizzle (8 x 16B columns)
#define SWZ128(o) ((o) ^ (((o) >> 3) & 0x70))
// 64B-row swizzle: col(0..3) ^= (row>>1)&3  -> conflict-free for 8-row ldmatrix phases
#define SWZ64(o)  ((o) ^ (((o) >> 3) & 0x30))

#define CP_ASYNC16(dst, src) \
    asm volatile("cp.async.cg.shared.global [%0], [%1], 16;" :: "r"(dst), "l"(src) : "memory")
#define CP_COMMIT() asm volatile("cp.async.commit_group;" ::: "memory")
#define CP_WAIT1()  asm volatile("cp.async.wait_group 1;" ::: "memory")

__device__ __forceinline__ void ldsm4(uint32_t* r, uint32_t a) {
    asm volatile("ldmatrix.sync.aligned.m8n8.x4.shared.b16 {%0,%1,%2,%3}, [%4];"
                 : "=r"(r[0]), "=r"(r[1]), "=r"(r[2]), "=r"(r[3]) : "r"(a));
}
__device__ __forceinline__ void ldsm2(uint32_t* r, uint32_t a) {
    asm volatile("ldmatrix.sync.aligned.m8n8.x2.shared.b16 {%0,%1}, [%2];"
                 : "=r"(r[0]), "=r"(r[1]) : "r"(a));
}
__device__ __forceinline__ void mma16816(float* c, const uint32_t* a, const uint32_t* b) {
    asm volatile(
        "mma.sync.aligned.m16n8k16.row.col.f32.f16.f16.f32 "
        "{%0,%1,%2,%3}, {%4,%5,%6,%7}, {%8,%9}, {%0,%1,%2,%3};"
        : "+f"(c[0]), "+f"(c[1]), "+f"(c[2]), "+f"(c[3])
        : "r"(a[0]), "r"(a[1]), "r"(a[2]), "r"(a[3]), "r"(b[0]), "r"(b[1]));
}

// ---------------------------------------------------------------------------
// Prepasses
// ---------------------------------------------------------------------------
__global__ __launch_bounds__(256) void cvt_round(
    const float* __restrict__ src, __half* __restrict__ dst, int n4)
{
    int i = blockIdx.x * blockDim.x + threadIdx.x;
    if (i >= n4) return;
    float4 v = ((const float4*)src)[i];
    __half2 h[2];
    h[0] = __floats2half2_rn(v.x, v.y);
    h[1] = __floats2half2_rn(v.z, v.w);
    *(uint2*)(dst + (size_t)i * 4) = *(uint2*)h;
}

__global__ __launch_bounds__(256) void cvt_split(
    const float* __restrict__ src,
    __half* __restrict__ hi, __half* __restrict__ lo, int n4)
{
    int i = blockIdx.x * blockDim.x + threadIdx.x;
    if (i >= n4) return;
    float4 v = ((const float4*)src)[i];
    __half2 h[2], l[2];
    h[0] = __floats2half2_rn(v.x, v.y);
    h[1] = __floats2half2_rn(v.z, v.w);
    float2 b0 = __half22float2(h[0]);
    float2 b1 = __half22float2(h[1]);
    l[0] = __floats2half2_rn(v.x - b0.x, v.y - b0.y);
    l[1] = __floats2half2_rn(v.z - b1.x, v.w - b1.y);
    *(uint2*)(hi + (size_t)i * 4) = *(uint2*)h;
    *(uint2*)(lo + (size_t)i * 4) = *(uint2*)l;
}

// ---------------------------------------------------------------------------
// 2-product fp16 HMMA GEMM: C[M,N] = A[M,K] @ (Whi+Wlo)[N,K]^T + bias (opt ReLU)
// A single fp16 plane, W split hi/lo. CTA 128x128, BK=32, 256 thr, warp 64x32.
// SMEM stage (24KB): A 128 rows x 64B (SWZ64); W rows [hi 64B | lo 64B] (SWZ128).
// ---------------------------------------------------------------------------
static constexpr int A_BYTES  = 8192;
static constexpr int STAGE_B  = 24576;
static constexpr int NSTAGE   = 3;
static constexpr int SMEM_BYTES = NSTAGE * STAGE_B;   // 72 KB -> 2 CTAs/SM

template <bool RELU>
__global__ __launch_bounds__(256, 2) void gemm_mma(
    const __half* __restrict__ A,
    const __half* __restrict__ Whi,
    const __half* __restrict__ Wlo,
    const float* __restrict__ bias,
    float* __restrict__ C,
    int N, int K)
{
    extern __shared__ __align__(1024) char smem[];
    const uint32_t sbase = smem_to_u32(smem);
    const int tid = threadIdx.x;
    const int lane = tid & 31, w = tid >> 5;
    const int m0 = blockIdx.y * 128, n0 = blockIdx.x * 128;
    const int mw = (w & 1) * 64;
    const int nw = (w >> 1) * 32;

    float acc[4][4][4];
#pragma unroll
    for (int i = 0; i < 4; i++)
#pragma unroll
        for (int j = 0; j < 4; j++)
#pragma unroll
            for (int r = 0; r < 4; r++) acc[i][j][r] = 0.0f;

    auto issue = [&](int kt, int s) {
        const uint32_t sA = sbase + s * STAGE_B;
        // A: 512 x 16B chunks, 2 per thread
#pragma unroll
        for (int p = 0; p < 2; p++) {
            const int c = tid + p * 256;
            const int row = c >> 2, sub = c & 3;
            const __half* src = A + (size_t)(m0 + row) * K + kt * 32 + sub * 8;
            CP_ASYNC16(sA + SWZ64((uint32_t)(row * 64 + sub * 16)), src);
        }
        // W: 1024 x 16B chunks, 4 per thread (hi|lo per row)
#pragma unroll
        for (int p = 0; p < 4; p++) {
            const int c = tid + p * 256;
            const int row = c >> 3, sub = c & 7;
            const __half* src =
                (sub < 4 ? Whi : Wlo) + (size_t)(n0 + row) * K + kt * 32 + (sub & 3) * 8;
            CP_ASYNC16(sA + A_BYTES + SWZ128((uint32_t)(row * 128 + sub * 16)), src);
        }
        CP_COMMIT();
    };

    auto compute = [&](int s) {
        const uint32_t aA = sbase + s * STAGE_B;
        const uint32_t aB = aA + A_BYTES;
#pragma unroll
        for (int ks = 0; ks < 2; ks++) {
            uint32_t a[4][4], bh[4][2], bl[4][2];
#pragma unroll
            for (int i = 0; i < 4; i++) {
                const int r = mw + i * 16 + (lane & 15);
                const uint32_t off = (uint32_t)(ks * 32 + ((lane >> 4) << 4));
                ldsm4(a[i], aA + SWZ64((uint32_t)(r * 64) + off));
            }
#pragma unroll
            for (int j = 0; j < 4; j++) {
                const int r = nw + j * 8 + (lane & 7);
                const uint32_t off = (uint32_t)(ks * 32 + ((lane >> 3) & 1) * 16);
                ldsm2(bh[j], aB + SWZ128((uint32_t)(r * 128) + off));
                ldsm2(bl[j], aB + SWZ128((uint32_t)(r * 128) + off + 64));
            }
#pragma unroll
            for (int i = 0; i < 4; i++)
#pragma unroll
                for (int j = 0; j < 4; j++) {
                    mma16816(acc[i][j], a[i], bh[j]);
                    mma16816(acc[i][j], a[i], bl[j]);
                }
        }
    };

    const int NT = K / 32;
    issue(0, 0);
    issue(1, 1);

#pragma unroll 1
    for (int kt = 0; kt < NT; kt++) {
        const int s = kt % 3;
        CP_WAIT1();
        __syncthreads();
        if (kt + 2 < NT) issue(kt + 2, (kt + 2) % 3);
        compute(s);
    }

    // epilogue
#pragma unroll
    for (int i = 0; i < 4; i++) {
        const int mrow = m0 + mw + i * 16 + (lane >> 2);
#pragma unroll
        for (int j = 0; j < 4; j++) {
            const int ncol = n0 + nw + j * 8 + (lane & 3) * 2;
            const float b0 = bias[ncol], b1 = bias[ncol + 1];
            float2 v0 = make_float2(acc[i][j][0] + b0, acc[i][j][1] + b1);
            float2 v1 = make_float2(acc[i][j][2] + b0, acc[i][j][3] + b1);
            if (RELU) {
                v0.x = fmaxf(v0.x, 0.f); v0.y = fmaxf(v0.y, 0.f);
                v1.x = fmaxf(v1.x, 0.f); v1.y = fmaxf(v1.y, 0.f);
            }
            *(float2*)(C + (size_t)mrow * N + ncol) = v0;
            *(float2*)(C + (size_t)(mrow + 8) * N + ncol) = v1;
        }
    }
}

// ---------------------------------------------------------------------------
// Scan phase 1: local sequential scan within each chunk
// ---------------------------------------------------------------------------
__global__ __launch_bounds__(256) void scan_local(const float* __restrict__ plog)
{
    int t = blockIdx.x * blockDim.x + threadIdx.x;
    int d = t % DD;
    int c = (t / DD) % NCH;
    int b = t / (DD * NCH);

    float v  = expf(plog[d]);
    float th = expf(plog[DD + d]);
    float r  = expf(-v);
    float sn, cs;
    sincosf(th, &sn, &cs);
    float lre = r * cs, lim = r * sn;

    size_t base = ((size_t)(b * LSEQ + c * CH)) * DD + d;
    float2 s = make_float2(0.0f, 0.0f);
    float2 unext = g_u[base];
#pragma unroll 4
    for (int j = 0; j < CH; j++) {
        float2 u = unext;
        if (j + 1 < CH) unext = g_u[base + (size_t)(j + 1) * DD];
        float sre = fmaf(lre, s.x, fmaf(-lim, s.y, u.x));
        float sim = fmaf(lre, s.y, fmaf( lim, s.x, u.y));
        s = make_float2(sre, sim);
        g_u[base + (size_t)j * DD] = s;
    }
    g_last[(b * NCH + c) * DD + d] = s;
}

// ---------------------------------------------------------------------------
// Scan phase 2: carry scan across chunks
// ---------------------------------------------------------------------------
__global__ __launch_bounds__(256) void scan_carry(const float* __restrict__ plog)
{
    int t = blockIdx.x * blockDim.x + threadIdx.x;
    int d = t % DD;
    int b = t / DD;

    float v  = expf(plog[d]);
    float th = expf(plog[DD + d]);
    float Lr = expf(-(float)CH * v);
    float sn, cs;
    sincosf((float)CH * th, &sn, &cs);
    float Lre = Lr * cs, Lim = Lr * sn;

    float2 s = make_float2(0.0f, 0.0f);
    for (int k = 0; k < NCH; k++) {
        g_cin[(b * NCH + k) * DD + d] = s;
        float2 last = g_last[(b * NCH + k) * DD + d];
        float sre = fmaf(Lre, s.x, fmaf(-Lim, s.y, last.x));
        float sim = fmaf(Lre, s.y, fmaf( Lim, s.x, last.y));
        s = make_float2(sre, sim);
    }
}

// ---------------------------------------------------------------------------
// Scan phase 3: fixup + gamma, write GEMM2 A operand (single fp16 plane)
// ---------------------------------------------------------------------------
__global__ __launch_bounds__(256) void scan_fix(const float* __restrict__ plog)
{
    int t = blockIdx.x * blockDim.x + threadIdx.x;
    int d = t % DD;
    int c = (t / DD) % NCH;
    int b = t / (DD * NCH);

    float v  = expf(plog[d]);
    float th = expf(plog[DD + d]);
    float g  = expf(plog[2 * DD + d]);
    float r  = expf(-v);
    float sn, cs;
    sincosf(th, &sn, &cs);
    float lre = r * cs, lim = r * sn;

    float2 cin = g_cin[(b * NCH + c) * DD + d];
    float pre = lre, pim = lim;

    size_t base = ((size_t)(b * LSEQ + c * CH)) * DD + d;
    size_t rbase = ((size_t)(b * LSEQ + c * CH)) * (2 * DD);

#pragma unroll 4
    for (int j = 0; j < CH; j++) {
        float2 x = g_u[base + (size_t)j * DD];
        float xre = g * (x.x + pre * cin.x - pim * cin.y);
        float xim = g * (x.y + pre * cin.y + pim * cin.x);
        size_t o0 = rbase + (size_t)j * (2 * DD) + d;
        g_xrh[o0]      = __float2half(xre);
        g_xrh[o0 + DD] = __float2half(xim);
        float npre = pre * lre - pim * lim;
        pim = pre * lim + pim * lre;
        pre = npre;
    }
}

// ---------------------------------------------------------------------------
extern "C" void kernel_launch(void* const* d_in, const int* in_sizes, int n_in,
                              void* d_out, int out_size)
{
    const float* inputs = (const float*)d_in[0];
    const float* Wi     = (const float*)d_in[1];
    const float* bi     = (const float*)d_in[2];
    const float* Wo     = (const float*)d_in[3];
    const float* bo     = (const float*)d_in[4];
    const float* plog   = (const float*)d_in[5];

    void *up, *ih, *wih, *wil, *woh, *wol, *xh;
    cudaGetSymbolAddress(&up,  g_u);
    cudaGetSymbolAddress(&ih,  g_inh);
    cudaGetSymbolAddress(&wih, g_wihi);  cudaGetSymbolAddress(&wil, g_wilo);
    cudaGetSymbolAddress(&woh, g_wohi);  cudaGetSymbolAddress(&wol, g_wolo);
    cudaGetSymbolAddress(&xh,  g_xrh);

    cudaFuncSetAttribute(gemm_mma<false>, cudaFuncAttributeMaxDynamicSharedMemorySize, SMEM_BYTES);
    cudaFuncSetAttribute(gemm_mma<true>,  cudaFuncAttributeMaxDynamicSharedMemorySize, SMEM_BYTES);

    // prepasses
    {
        int n4 = MROWS * DD / 4;
        cvt_round<<<(n4 + 255) / 256, 256>>>(inputs, (__half*)ih, n4);
        n4 = 2 * DD * DD / 4;
        cvt_split<<<(n4 + 255) / 256, 256>>>(Wi, (__half*)wih, (__half*)wil, n4);
        cvt_split<<<(n4 + 255) / 256, 256>>>(Wo, (__half*)woh, (__half*)wol, n4);
    }

    // GEMM1: u = inputs @ Wi^T + bi  -> g_u
    gemm_mma<false><<<dim3((2 * DD) / 128, MROWS / 128), 256, SMEM_BYTES>>>(
        (const __half*)ih, (const __half*)wih, (const __half*)wil,
        bi, (float*)up, 2 * DD, DD);

    // Scan
    scan_local<<<(BSZ * NCH * DD) / 256, 256>>>(plog);
    scan_carry<<<(BSZ * DD) / 256, 256>>>(plog);
    scan_fix<<<(BSZ * NCH * DD) / 256, 256>>>(plog);

    // GEMM2: out = relu(xr @ Wo^T + bo)
    gemm_mma<true><<<dim3(DD / 128, MROWS / 128), 256, SMEM_BYTES>>>(
        (const __half*)xh, (const __half*)woh, (const __half*)wol,
        bo, (float*)d_out, DD, 2 * DD);
}

// round 6
// speedup vs baseline: 2.1932x; 1.4453x over previous
#include <cuda_runtime.h>
#include <cuda_fp16.h>
#include <math.h>
#include <cstdint>

#define BSZ 4
#define LSEQ 4096
#define DD 1024
#define CH 64
#define NCH (LSEQ / CH)
#define MROWS (BSZ * LSEQ)

// ---------------------------------------------------------------------------
// Scratch (device globals)
// ---------------------------------------------------------------------------
__device__ float2 g_u[(size_t)BSZ * LSEQ * DD];        // GEMM1 out (complex interleaved)
__device__ float2 g_last[BSZ * NCH * DD];
__device__ float2 g_cin[BSZ * NCH * DD];

__device__ __half g_inh[(size_t)MROWS * DD];           // inputs fp16
__device__ __half g_wih[(size_t)2 * DD * DD];          // Wi fp16
__device__ __half g_woh[(size_t)DD * 2 * DD];          // Wo fp16
__device__ __half g_xrh[(size_t)MROWS * 2 * DD];       // GEMM2 A ([re|im]) fp16

// ---------------------------------------------------------------------------
// helpers
// ---------------------------------------------------------------------------
__device__ __forceinline__ uint32_t smem_to_u32(const void* p) {
    uint32_t a;
    asm("{ .reg .u64 t; cvta.to.shared.u64 t, %1; cvt.u32.u64 %0, t; }" : "=r"(a) : "l"(p));
    return a;
}
#define SWZ128(o) ((o) ^ (((o) >> 3) & 0x70))

#define CP_ASYNC16(dst, src) \
    asm volatile("cp.async.cg.shared.global [%0], [%1], 16;" :: "r"(dst), "l"(src) : "memory")
#define CP_COMMIT() asm volatile("cp.async.commit_group;" ::: "memory")
#define CP_WAIT1()  asm volatile("cp.async.wait_group 1;" ::: "memory")

__device__ __forceinline__ void ldsm4(uint32_t* r, uint32_t a) {
    asm volatile("ldmatrix.sync.aligned.m8n8.x4.shared.b16 {%0,%1,%2,%3}, [%4];"
                 : "=r"(r[0]), "=r"(r[1]), "=r"(r[2]), "=r"(r[3]) : "r"(a));
}
__device__ __forceinline__ void mma16816(float* c, const uint32_t* a, const uint32_t* b) {
    asm volatile(
        "mma.sync.aligned.m16n8k16.row.col.f32.f16.f16.f32 "
        "{%0,%1,%2,%3}, {%4,%5,%6,%7}, {%8,%9}, {%0,%1,%2,%3};"
        : "+f"(c[0]), "+f"(c[1]), "+f"(c[2]), "+f"(c[3])
        : "r"(a[0]), "r"(a[1]), "r"(a[2]), "r"(a[3]), "r"(b[0]), "r"(b[1]));
}

// ---------------------------------------------------------------------------
// Prepass: fp32 -> fp16 round
// ---------------------------------------------------------------------------
__global__ __launch_bounds__(256) void cvt_round(
    const float* __restrict__ src, __half* __restrict__ dst, int n4)
{
    int i = blockIdx.x * blockDim.x + threadIdx.x;
    if (i >= n4) return;
    float4 v = ((const float4*)src)[i];
    __half2 h[2];
    h[0] = __floats2half2_rn(v.x, v.y);
    h[1] = __floats2half2_rn(v.z, v.w);
    *(uint2*)(dst + (size_t)i * 4) = *(uint2*)h;
}

// ---------------------------------------------------------------------------
// fp16 HMMA GEMM: C[M,N] = A[M,K] @ W[N,K]^T + bias (opt ReLU)
// CTA 128x128, BK=64, 256 thr / 8 warps, warp tile 64x32, 3-stage cp.async.
// Stage (32KB): A 128 rows x 128B SW128, W same at +16KB.
// ---------------------------------------------------------------------------
static constexpr int A_BYTES  = 16384;
static constexpr int STAGE_B  = 32768;
static constexpr int NSTAGE   = 3;
static constexpr int SMEM_BYTES = NSTAGE * STAGE_B;   // 96 KB -> 2 CTAs/SM

template <bool RELU, int K>
__global__ __launch_bounds__(256, 2) void gemm_mma(
    const __half* __restrict__ A,
    const __half* __restrict__ W,
    const float* __restrict__ bias,
    float* __restrict__ C,
    int N)
{
    extern __shared__ __align__(1024) char smem[];
    const uint32_t sbase = smem_to_u32(smem);
    const int tid = threadIdx.x;
    const int lane = tid & 31, w = tid >> 5;
    const int m0 = blockIdx.y * 128, n0 = blockIdx.x * 128;
    const int mw = (w & 1) * 64;
    const int nw = (w >> 1) * 32;

    float acc[4][4][4];
#pragma unroll
    for (int i = 0; i < 4; i++)
#pragma unroll
        for (int j = 0; j < 4; j++)
#pragma unroll
            for (int r = 0; r < 4; r++) acc[i][j][r] = 0.0f;

    // loader: per stage, A and W each 1024 x 16B chunks, 4 per thread each
    const int lrow = tid >> 1;                 // two threads per 128B row
    const int lsub2 = (tid & 1) * 4;           // chunks 0-3 or 4-7
    const __half* Abase = A + (size_t)(m0 + lrow) * K + lsub2 * 8;
    const __half* Wbase = W + (size_t)(n0 + lrow) * K + lsub2 * 8;

    auto issue = [&](int kt, int s) {
        const uint32_t sA = sbase + s * STAGE_B;
        const __half* as = Abase + kt * 64;
        const __half* ws = Wbase + kt * 64;
#pragma unroll
        for (int p = 0; p < 4; p++) {
            const uint32_t d = SWZ128((uint32_t)(lrow * 128 + (lsub2 + p) * 16));
            CP_ASYNC16(sA + d, as + p * 8);
            CP_ASYNC16(sA + A_BYTES + d, ws + p * 8);
        }
        CP_COMMIT();
    };

    auto compute = [&](int s) {
        const uint32_t aA = sbase + s * STAGE_B;
        const uint32_t aB = aA + A_BYTES;
#pragma unroll
        for (int ks = 0; ks < 4; ks++) {
            uint32_t a[4][4], b[2][4];
#pragma unroll
            for (int i = 0; i < 4; i++) {
                const int r = mw + i * 16 + (lane & 15);
                const uint32_t off = (uint32_t)(ks * 32 + ((lane >> 4) << 4));
                ldsm4(a[i], aA + SWZ128((uint32_t)(r * 128) + off));
            }
#pragma unroll
            for (int jj = 0; jj < 2; jj++) {
                const int r = nw + jj * 16 + ((lane >> 4) << 3) + (lane & 7);
                const uint32_t off = (uint32_t)(ks * 32 + (((lane >> 3) & 1) << 4));
                ldsm4(b[jj], aB + SWZ128((uint32_t)(r * 128) + off));
            }
#pragma unroll
            for (int i = 0; i < 4; i++)
#pragma unroll
                for (int jj = 0; jj < 2; jj++) {
                    mma16816(acc[i][jj * 2 + 0], a[i], b[jj] + 0);
                    mma16816(acc[i][jj * 2 + 1], a[i], b[jj] + 2);
                }
        }
    };

    constexpr int NT = K / 64;
    issue(0, 0);
    issue(1, 1);

#pragma unroll 1
    for (int kt = 0; kt < NT; kt++) {
        const int s = kt % 3;
        CP_WAIT1();
        __syncthreads();
        if (kt + 2 < NT) issue(kt + 2, (kt + 2) % 3);
        compute(s);
    }

    // epilogue
#pragma unroll
    for (int i = 0; i < 4; i++) {
        const int mrow = m0 + mw + i * 16 + (lane >> 2);
#pragma unroll
        for (int j = 0; j < 4; j++) {
            const int ncol = n0 + nw + j * 8 + (lane & 3) * 2;
            const float b0 = bias[ncol], b1 = bias[ncol + 1];
            float2 v0 = make_float2(acc[i][j][0] + b0, acc[i][j][1] + b1);
            float2 v1 = make_float2(acc[i][j][2] + b0, acc[i][j][3] + b1);
            if (RELU) {
                v0.x = fmaxf(v0.x, 0.f); v0.y = fmaxf(v0.y, 0.f);
                v1.x = fmaxf(v1.x, 0.f); v1.y = fmaxf(v1.y, 0.f);
            }
            *(float2*)(C + (size_t)mrow * N + ncol) = v0;
            *(float2*)(C + (size_t)(mrow + 8) * N + ncol) = v1;
        }
    }
}

// ---------------------------------------------------------------------------
// Scan phase 1: local sequential scan within each chunk
// ---------------------------------------------------------------------------
__global__ __launch_bounds__(256) void scan_local(const float* __restrict__ plog)
{
    int t = blockIdx.x * blockDim.x + threadIdx.x;
    int d = t % DD;
    int c = (t / DD) % NCH;
    int b = t / (DD * NCH);

    float v  = expf(plog[d]);
    float th = expf(plog[DD + d]);
    float r  = expf(-v);
    float sn, cs;
    sincosf(th, &sn, &cs);
    float lre = r * cs, lim = r * sn;

    size_t base = ((size_t)(b * LSEQ + c * CH)) * DD + d;
    float2 s = make_float2(0.0f, 0.0f);
    float2 unext = g_u[base];
#pragma unroll 4
    for (int j = 0; j < CH; j++) {
        float2 u = unext;
        if (j + 1 < CH) unext = g_u[base + (size_t)(j + 1) * DD];
        float sre = fmaf(lre, s.x, fmaf(-lim, s.y, u.x));
        float sim = fmaf(lre, s.y, fmaf( lim, s.x, u.y));
        s = make_float2(sre, sim);
        g_u[base + (size_t)j * DD] = s;
    }
    g_last[(b * NCH + c) * DD + d] = s;
}

// ---------------------------------------------------------------------------
// Scan phase 2: carry scan across chunks
// ---------------------------------------------------------------------------
__global__ __launch_bounds__(256) void scan_carry(const float* __restrict__ plog)
{
    int t = blockIdx.x * blockDim.x + threadIdx.x;
    int d = t % DD;
    int b = t / DD;

    float v  = expf(plog[d]);
    float th = expf(plog[DD + d]);
    float Lr = expf(-(float)CH * v);
    float sn, cs;
    sincosf((float)CH * th, &sn, &cs);
    float Lre = Lr * cs, Lim = Lr * sn;

    float2 s = make_float2(0.0f, 0.0f);
    for (int k = 0; k < NCH; k++) {
        g_cin[(b * NCH + k) * DD + d] = s;
        float2 last = g_last[(b * NCH + k) * DD + d];
        float sre = fmaf(Lre, s.x, fmaf(-Lim, s.y, last.x));
        float sim = fmaf(Lre, s.y, fmaf( Lim, s.x, last.y));
        s = make_float2(sre, sim);
    }
}

// ---------------------------------------------------------------------------
// Scan phase 3: fixup + gamma, write GEMM2 A operand (fp16 plane)
// ---------------------------------------------------------------------------
__global__ __launch_bounds__(256) void scan_fix(const float* __restrict__ plog)
{
    int t = blockIdx.x * blockDim.x + threadIdx.x;
    int d = t % DD;
    int c = (t / DD) % NCH;
    int b = t / (DD * NCH);

    float v  = expf(plog[d]);
    float th = expf(plog[DD + d]);
    float g  = expf(plog[2 * DD + d]);
    float r  = expf(-v);
    float sn, cs;
    sincosf(th, &sn, &cs);
    float lre = r * cs, lim = r * sn;

    float2 cin = g_cin[(b * NCH + c) * DD + d];
    float pre = lre, pim = lim;

    size_t base = ((size_t)(b * LSEQ + c * CH)) * DD + d;
    size_t rbase = ((size_t)(b * LSEQ + c * CH)) * (2 * DD);

#pragma unroll 4
    for (int j = 0; j < CH; j++) {
        float2 x = g_u[base + (size_t)j * DD];
        float xre = g * (x.x + pre * cin.x - pim * cin.y);
        float xim = g * (x.y + pre * cin.y + pim * cin.x);
        size_t o0 = rbase + (size_t)j * (2 * DD) + d;
        g_xrh[o0]      = __float2half(xre);
        g_xrh[o0 + DD] = __float2half(xim);
        float npre = pre * lre - pim * lim;
        pim = pre * lim + pim * lre;
        pre = npre;
    }
}

// ---------------------------------------------------------------------------
extern "C" void kernel_launch(void* const* d_in, const int* in_sizes, int n_in,
                              void* d_out, int out_size)
{
    const float* inputs = (const float*)d_in[0];
    const float* Wi     = (const float*)d_in[1];
    const float* bi     = (const float*)d_in[2];
    const float* Wo     = (const float*)d_in[3];
    const float* bo     = (const float*)d_in[4];
    const float* plog   = (const float*)d_in[5];

    void *up, *ih, *wih, *woh, *xh;
    cudaGetSymbolAddress(&up,  g_u);
    cudaGetSymbolAddress(&ih,  g_inh);
    cudaGetSymbolAddress(&wih, g_wih);
    cudaGetSymbolAddress(&woh, g_woh);
    cudaGetSymbolAddress(&xh,  g_xrh);

    cudaFuncSetAttribute(gemm_mma<false, DD>,
                         cudaFuncAttributeMaxDynamicSharedMemorySize, SMEM_BYTES);
    cudaFuncSetAttribute(gemm_mma<true, 2 * DD>,
                         cudaFuncAttributeMaxDynamicSharedMemorySize, SMEM_BYTES);

    // prepasses: fp32 -> fp16
    {
        int n4 = MROWS * DD / 4;
        cvt_round<<<(n4 + 255) / 256, 256>>>(inputs, (__half*)ih, n4);
        n4 = 2 * DD * DD / 4;
        cvt_round<<<(n4 + 255) / 256, 256>>>(Wi, (__half*)wih, n4);
        cvt_round<<<(n4 + 255) / 256, 256>>>(Wo, (__half*)woh, n4);
    }

    // GEMM1: u = inputs @ Wi^T + bi  -> g_u
    gemm_mma<false, DD><<<dim3((2 * DD) / 128, MROWS / 128), 256, SMEM_BYTES>>>(
        (const __half*)ih, (const __half*)wih, bi, (float*)up, 2 * DD);

    // Scan
    scan_local<<<(BSZ * NCH * DD) / 256, 256>>>(plog);
    scan_carry<<<(BSZ * DD) / 256, 256>>>(plog);
    scan_fix<<<(BSZ * NCH * DD) / 256, 256>>>(plog);

    // GEMM2: out = relu(xr @ Wo^T + bo)
    gemm_mma<true, 2 * DD><<<dim3(DD / 128, MROWS / 128), 256, SMEM_BYTES>>>(
        (const __half*)xh, (const __half*)woh, bo, (float*)d_out, DD);
}

// round 7
// speedup vs baseline: 2.4520x; 1.1180x over previous
#include <cuda_runtime.h>
#include <cuda_fp16.h>
#include <math.h>
#include <cstdint>

#define BSZ 4
#define LSEQ 4096
#define DD 1024
#define CH 64
#define NCH (LSEQ / CH)
#define MROWS (BSZ * LSEQ)

// ---------------------------------------------------------------------------
// Scratch (device globals)
// ---------------------------------------------------------------------------
__device__ float2 g_u[(size_t)BSZ * LSEQ * DD];        // GEMM1 out (complex interleaved)
__device__ float2 g_last[BSZ * NCH * DD];
__device__ float2 g_cin[BSZ * NCH * DD];

__device__ __half g_inh[(size_t)MROWS * DD];           // inputs fp16
__device__ __half g_wih[(size_t)2 * DD * DD];          // Wi fp16
__device__ __half g_woh[(size_t)DD * 2 * DD];          // Wo fp16
__device__ __half g_xrh[(size_t)MROWS * 2 * DD];       // GEMM2 A ([re|im]) fp16

// ---------------------------------------------------------------------------
// helpers
// ---------------------------------------------------------------------------
__device__ __forceinline__ uint32_t smem_to_u32(const void* p) {
    uint32_t a;
    asm("{ .reg .u64 t; cvta.to.shared.u64 t, %1; cvt.u32.u64 %0, t; }" : "=r"(a) : "l"(p));
    return a;
}
#define SWZ128(o) ((o) ^ (((o) >> 3) & 0x70))

#define CP_ASYNC16(dst, src) \
    asm volatile("cp.async.cg.shared.global [%0], [%1], 16;" :: "r"(dst), "l"(src) : "memory")
#define CP_COMMIT() asm volatile("cp.async.commit_group;" ::: "memory")
#define CP_WAIT1()  asm volatile("cp.async.wait_group 1;" ::: "memory")
#define CP_WAIT0()  asm volatile("cp.async.wait_group 0;" ::: "memory")

__device__ __forceinline__ void ldsm4(uint32_t* r, uint32_t a) {
    asm volatile("ldmatrix.sync.aligned.m8n8.x4.shared.b16 {%0,%1,%2,%3}, [%4];"
                 : "=r"(r[0]), "=r"(r[1]), "=r"(r[2]), "=r"(r[3]) : "r"(a));
}
__device__ __forceinline__ void mma16816(float* c, const uint32_t* a, const uint32_t* b) {
    asm volatile(
        "mma.sync.aligned.m16n8k16.row.col.f32.f16.f16.f32 "
        "{%0,%1,%2,%3}, {%4,%5,%6,%7}, {%8,%9}, {%0,%1,%2,%3};"
        : "+f"(c[0]), "+f"(c[1]), "+f"(c[2]), "+f"(c[3])
        : "r"(a[0]), "r"(a[1]), "r"(a[2]), "r"(a[3]), "r"(b[0]), "r"(b[1]));
}

// ---------------------------------------------------------------------------
// Prepass: fp32 -> fp16 round
// ---------------------------------------------------------------------------
__global__ __launch_bounds__(256) void cvt_round(
    const float* __restrict__ src, __half* __restrict__ dst, int n4)
{
    int i = blockIdx.x * blockDim.x + threadIdx.x;
    if (i >= n4) return;
    float4 v = ((const float4*)src)[i];
    __half2 h[2];
    h[0] = __floats2half2_rn(v.x, v.y);
    h[1] = __floats2half2_rn(v.z, v.w);
    *(uint2*)(dst + (size_t)i * 4) = *(uint2*)h;
}

// ---------------------------------------------------------------------------
// fp16 HMMA GEMM: C[M,N] = A[M,K] @ W[N,K]^T + bias (opt ReLU)
// CTA 128x256, BK=64, 256 thr / 8 warps (2Mx4N), warp tile 64x64.
// 3-stage cp.async; stage (48KB): A 128 rows x 128B SW128, W 256 rows at +16KB.
// ---------------------------------------------------------------------------
static constexpr int A_BYTES  = 16384;
static constexpr int B_BYTES  = 32768;
static constexpr int STAGE_B  = A_BYTES + B_BYTES;    // 48 KB
static constexpr int NSTAGE   = 3;
static constexpr int SMEM_BYTES = NSTAGE * STAGE_B;   // 144 KB

template <bool RELU, int K>
__global__ __launch_bounds__(256, 1) void gemm_mma(
    const __half* __restrict__ A,
    const __half* __restrict__ W,
    const float* __restrict__ bias,
    float* __restrict__ C,
    int N)
{
    extern __shared__ __align__(1024) char smem[];
    const uint32_t sbase = smem_to_u32(smem);
    const int tid = threadIdx.x;
    const int lane = tid & 31, w = tid >> 5;
    const int m0 = blockIdx.y * 128, n0 = blockIdx.x * 256;
    const int mw = (w & 1) * 64;
    const int nw = (w >> 1) * 64;

    float acc[4][8][4];
#pragma unroll
    for (int i = 0; i < 4; i++)
#pragma unroll
        for (int j = 0; j < 8; j++)
#pragma unroll
            for (int r = 0; r < 4; r++) acc[i][j][r] = 0.0f;

    // loader mapping: chunk c -> row c>>3, 16B-col c&7
    const int lrow = tid >> 3;        // 0..31
    const int lsub = tid & 7;         // 0..7
    const __half* Abase = A + (size_t)(m0 + lrow) * K + lsub * 8;
    const __half* Wbase = W + (size_t)(n0 + lrow) * K + lsub * 8;
    const uint32_t ldst = SWZ128((uint32_t)(lrow * 128 + lsub * 16));

    auto issue = [&](int kt, int s) {
        const uint32_t sA = sbase + s * STAGE_B;
        const __half* as = Abase + kt * 64;
        const __half* ws = Wbase + kt * 64;
#pragma unroll
        for (int p = 0; p < 4; p++)   // A: rows lrow + 32p
            CP_ASYNC16(sA + ldst + (uint32_t)(p * 32 * 128), as + (size_t)(p * 32) * K);
#pragma unroll
        for (int p = 0; p < 8; p++)   // W: rows lrow + 32p
            CP_ASYNC16(sA + A_BYTES + ldst + (uint32_t)(p * 32 * 128), ws + (size_t)(p * 32) * K);
        CP_COMMIT();
    };

    auto compute = [&](int s) {
        const uint32_t aA = sbase + s * STAGE_B;
        const uint32_t aB = aA + A_BYTES;
#pragma unroll
        for (int ks = 0; ks < 4; ks++) {
            uint32_t a[4][4], b[4][4];
#pragma unroll
            for (int i = 0; i < 4; i++) {
                const int r = mw + i * 16 + (lane & 15);
                const uint32_t off = (uint32_t)(ks * 32 + ((lane >> 4) << 4));
                ldsm4(a[i], aA + SWZ128((uint32_t)(r * 128) + off));
            }
#pragma unroll
            for (int jj = 0; jj < 4; jj++) {
                const int r = nw + jj * 16 + ((lane >> 4) << 3) + (lane & 7);
                const uint32_t off = (uint32_t)(ks * 32 + (((lane >> 3) & 1) << 4));
                ldsm4(b[jj], aB + SWZ128((uint32_t)(r * 128) + off));
            }
#pragma unroll
            for (int i = 0; i < 4; i++)
#pragma unroll
                for (int jj = 0; jj < 4; jj++) {
                    mma16816(acc[i][jj * 2 + 0], a[i], b[jj] + 0);
                    mma16816(acc[i][jj * 2 + 1], a[i], b[jj] + 2);
                }
        }
    };

    constexpr int NT = K / 64;
    issue(0, 0);
    issue(1, 1);

#pragma unroll 1
    for (int kt = 0; kt < NT; kt++) {
        const int s = kt % 3;
        if (kt + 2 < NT) CP_WAIT1(); else CP_WAIT0();
        __syncthreads();
        if (kt + 2 < NT) issue(kt + 2, (kt + 2) % 3);
        compute(s);
    }

    // epilogue
#pragma unroll
    for (int i = 0; i < 4; i++) {
        const int mrow = m0 + mw + i * 16 + (lane >> 2);
#pragma unroll
        for (int j = 0; j < 8; j++) {
            const int ncol = n0 + nw + j * 8 + (lane & 3) * 2;
            const float b0 = bias[ncol], b1 = bias[ncol + 1];
            float2 v0 = make_float2(acc[i][j][0] + b0, acc[i][j][1] + b1);
            float2 v1 = make_float2(acc[i][j][2] + b0, acc[i][j][3] + b1);
            if (RELU) {
                v0.x = fmaxf(v0.x, 0.f); v0.y = fmaxf(v0.y, 0.f);
                v1.x = fmaxf(v1.x, 0.f); v1.y = fmaxf(v1.y, 0.f);
            }
            *(float2*)(C + (size_t)mrow * N + ncol) = v0;
            *(float2*)(C + (size_t)(mrow + 8) * N + ncol) = v1;
        }
    }
}

// ---------------------------------------------------------------------------
// Scan phase 1: local scan, 2 complex dims per thread (float4 path)
// ---------------------------------------------------------------------------
__global__ __launch_bounds__(256) void scan_local(const float* __restrict__ plog)
{
    int t = blockIdx.x * blockDim.x + threadIdx.x;   // B*NCH*(DD/2) threads
    int dh = t % (DD / 2);
    int c  = (t / (DD / 2)) % NCH;
    int b  = t / ((DD / 2) * NCH);
    int d0 = dh * 2;

    float v0 = expf(plog[d0]),      v1 = expf(plog[d0 + 1]);
    float t0 = expf(plog[DD + d0]), t1 = expf(plog[DD + d0 + 1]);
    float r0 = expf(-v0), r1 = expf(-v1);
    float s0, c0s, s1, c1s;
    sincosf(t0, &s0, &c0s);
    sincosf(t1, &s1, &c1s);
    float lre0 = r0 * c0s, lim0 = r0 * s0;
    float lre1 = r1 * c1s, lim1 = r1 * s1;

    size_t base = ((size_t)(b * LSEQ + c * CH)) * DD + d0;   // float2 units
    float4 s = make_float4(0.f, 0.f, 0.f, 0.f);
#pragma unroll 4
    for (int j = 0; j < CH; j++) {
        float4 u = *(const float4*)(g_u + base + (size_t)j * DD);
        float a0 = fmaf(lre0, s.x, fmaf(-lim0, s.y, u.x));
        float a1 = fmaf(lre0, s.y, fmaf( lim0, s.x, u.y));
        float a2 = fmaf(lre1, s.z, fmaf(-lim1, s.w, u.z));
        float a3 = fmaf(lre1, s.w, fmaf( lim1, s.z, u.w));
        s = make_float4(a0, a1, a2, a3);
        *(float4*)(g_u + base + (size_t)j * DD) = s;
    }
    *(float4*)(g_last + (size_t)(b * NCH + c) * DD + d0) = s;
}

// ---------------------------------------------------------------------------
// Scan phase 2: carry scan across chunks (2 dims per thread)
// ---------------------------------------------------------------------------
__global__ __launch_bounds__(256) void scan_carry(const float* __restrict__ plog)
{
    int t = blockIdx.x * blockDim.x + threadIdx.x;   // B*(DD/2) threads
    int dh = t % (DD / 2);
    int b  = t / (DD / 2);
    int d0 = dh * 2;

    float v0 = expf(plog[d0]),      v1 = expf(plog[d0 + 1]);
    float t0 = expf(plog[DD + d0]), t1 = expf(plog[DD + d0 + 1]);
    float Lr0 = expf(-(float)CH * v0), Lr1 = expf(-(float)CH * v1);
    float s0, c0s, s1, c1s;
    sincosf((float)CH * t0, &s0, &c0s);
    sincosf((float)CH * t1, &s1, &c1s);
    float Lre0 = Lr0 * c0s, Lim0 = Lr0 * s0;
    float Lre1 = Lr1 * c1s, Lim1 = Lr1 * s1;

    float4 s = make_float4(0.f, 0.f, 0.f, 0.f);
    for (int k = 0; k < NCH; k++) {
        size_t idx = (size_t)(b * NCH + k) * DD + d0;
        *(float4*)(g_cin + idx) = s;
        float4 last = *(const float4*)(g_last + idx);
        float a0 = fmaf(Lre0, s.x, fmaf(-Lim0, s.y, last.x));
        float a1 = fmaf(Lre0, s.y, fmaf( Lim0, s.x, last.y));
        float a2 = fmaf(Lre1, s.z, fmaf(-Lim1, s.w, last.z));
        float a3 = fmaf(Lre1, s.w, fmaf( Lim1, s.z, last.w));
        s = make_float4(a0, a1, a2, a3);
    }
}

// ---------------------------------------------------------------------------
// Scan phase 3: fixup + gamma, write GEMM2 A operand (fp16, [re|im])
// ---------------------------------------------------------------------------
__global__ __launch_bounds__(256) void scan_fix(const float* __restrict__ plog)
{
    int t = blockIdx.x * blockDim.x + threadIdx.x;   // B*NCH*(DD/2) threads
    int dh = t % (DD / 2);
    int c  = (t / (DD / 2)) % NCH;
    int b  = t / ((DD / 2) * NCH);
    int d0 = dh * 2;

    float v0 = expf(plog[d0]),      v1 = expf(plog[d0 + 1]);
    float t0 = expf(plog[DD + d0]), t1 = expf(plog[DD + d0 + 1]);
    float g0 = expf(plog[2 * DD + d0]), g1 = expf(plog[2 * DD + d0 + 1]);
    float r0 = expf(-v0), r1 = expf(-v1);
    float s0, c0s, s1, c1s;
    sincosf(t0, &s0, &c0s);
    sincosf(t1, &s1, &c1s);
    float lre0 = r0 * c0s, lim0 = r0 * s0;
    float lre1 = r1 * c1s, lim1 = r1 * s1;

    float4 cin = *(const float4*)(g_cin + (size_t)(b * NCH + c) * DD + d0);
    float pre0 = lre0, pim0 = lim0;
    float pre1 = lre1, pim1 = lim1;

    size_t base  = ((size_t)(b * LSEQ + c * CH)) * DD + d0;
    size_t rbase = ((size_t)(b * LSEQ + c * CH)) * (2 * DD);

#pragma unroll 4
    for (int j = 0; j < CH; j++) {
        float4 x = *(const float4*)(g_u + base + (size_t)j * DD);
        float xre0 = g0 * (x.x + pre0 * cin.x - pim0 * cin.y);
        float xim0 = g0 * (x.y + pre0 * cin.y + pim0 * cin.x);
        float xre1 = g1 * (x.z + pre1 * cin.z - pim1 * cin.w);
        float xim1 = g1 * (x.w + pre1 * cin.w + pim1 * cin.z);
        size_t o = rbase + (size_t)j * (2 * DD) + d0;
        __half2 hre = __floats2half2_rn(xre0, xre1);
        __half2 him = __floats2half2_rn(xim0, xim1);
        *(uint32_t*)(g_xrh + o)      = *(uint32_t*)&hre;
        *(uint32_t*)(g_xrh + o + DD) = *(uint32_t*)&him;
        float n0 = pre0 * lre0 - pim0 * lim0;
        pim0 = pre0 * lim0 + pim0 * lre0; pre0 = n0;
        float n1 = pre1 * lre1 - pim1 * lim1;
        pim1 = pre1 * lim1 + pim1 * lre1; pre1 = n1;
    }
}

// ---------------------------------------------------------------------------
extern "C" void kernel_launch(void* const* d_in, const int* in_sizes, int n_in,
                              void* d_out, int out_size)
{
    const float* inputs = (const float*)d_in[0];
    const float* Wi     = (const float*)d_in[1];
    const float* bi     = (const float*)d_in[2];
    const float* Wo     = (const float*)d_in[3];
    const float* bo     = (const float*)d_in[4];
    const float* plog   = (const float*)d_in[5];

    void *up, *ih, *wih, *woh, *xh;
    cudaGetSymbolAddress(&up,  g_u);
    cudaGetSymbolAddress(&ih,  g_inh);
    cudaGetSymbolAddress(&wih, g_wih);
    cudaGetSymbolAddress(&woh, g_woh);
    cudaGetSymbolAddress(&xh,  g_xrh);

    cudaFuncSetAttribute(gemm_mma<false, DD>,
                         cudaFuncAttributeMaxDynamicSharedMemorySize, SMEM_BYTES);
    cudaFuncSetAttribute(gemm_mma<true, 2 * DD>,
                         cudaFuncAttributeMaxDynamicSharedMemorySize, SMEM_BYTES);

    // prepasses: fp32 -> fp16
    {
        int n4 = MROWS * DD / 4;
        cvt_round<<<(n4 + 255) / 256, 256>>>(inputs, (__half*)ih, n4);
        n4 = 2 * DD * DD / 4;
        cvt_round<<<(n4 + 255) / 256, 256>>>(Wi, (__half*)wih, n4);
        cvt_round<<<(n4 + 255) / 256, 256>>>(Wo, (__half*)woh, n4);
    }

    // GEMM1: u = inputs @ Wi^T + bi  -> g_u
    gemm_mma<false, DD><<<dim3((2 * DD) / 256, MROWS / 128), 256, SMEM_BYTES>>>(
        (const __half*)ih, (const __half*)wih, bi, (float*)up, 2 * DD);

    // Scan
    scan_local<<<(BSZ * NCH * DD / 2) / 256, 256>>>(plog);
    scan_carry<<<(BSZ * DD / 2) / 256, 256>>>(plog);
    scan_fix<<<(BSZ * NCH * DD / 2) / 256, 256>>>(plog);

    // GEMM2: out = relu(xr @ Wo^T + bo)
    gemm_mma<true, 2 * DD><<<dim3(DD / 256, MROWS / 128), 256, SMEM_BYTES>>>(
        (const __half*)xh, (const __half*)woh, bo, (float*)d_out, DD);
}

// round 8
// speedup vs baseline: 2.7990x; 1.1416x over previous
#include <cuda_runtime.h>
#include <cuda_fp16.h>
#include <math.h>
#include <cstdint>

#define BSZ 4
#define LSEQ 4096
#define DD 1024
#define CH 64
#define NCH (LSEQ / CH)
#define MROWS (BSZ * LSEQ)

// ---------------------------------------------------------------------------
// Scratch (device globals)
// ---------------------------------------------------------------------------
__device__ __half g_uh[(size_t)MROWS * 2 * DD];        // GEMM1 out, fp16 interleaved complex
__device__ float2 g_last[BSZ * NCH * DD];
__device__ float2 g_cin[BSZ * NCH * DD];

__device__ __half g_inh[(size_t)MROWS * DD];           // inputs fp16
__device__ __half g_wih[(size_t)2 * DD * DD];          // Wi fp16
__device__ __half g_woh[(size_t)DD * 2 * DD];          // Wo fp16
__device__ __half g_xrh[(size_t)MROWS * 2 * DD];       // GEMM2 A ([re|im]) fp16

// ---------------------------------------------------------------------------
// helpers
// ---------------------------------------------------------------------------
__device__ __forceinline__ uint32_t smem_to_u32(const void* p) {
    uint32_t a;
    asm("{ .reg .u64 t; cvta.to.shared.u64 t, %1; cvt.u32.u64 %0, t; }" : "=r"(a) : "l"(p));
    return a;
}
#define SWZ128(o) ((o) ^ (((o) >> 3) & 0x70))

#define CP_ASYNC16(dst, src) \
    asm volatile("cp.async.cg.shared.global [%0], [%1], 16;" :: "r"(dst), "l"(src) : "memory")
#define CP_COMMIT() asm volatile("cp.async.commit_group;" ::: "memory")
#define CP_WAIT0()  asm volatile("cp.async.wait_group 0;" ::: "memory")

__device__ __forceinline__ void ldsm4(uint32_t* r, uint32_t a) {
    asm volatile("ldmatrix.sync.aligned.m8n8.x4.shared.b16 {%0,%1,%2,%3}, [%4];"
                 : "=r"(r[0]), "=r"(r[1]), "=r"(r[2]), "=r"(r[3]) : "r"(a));
}
__device__ __forceinline__ void mma16816(float* c, const uint32_t* a, const uint32_t* b) {
    asm volatile(
        "mma.sync.aligned.m16n8k16.row.col.f32.f16.f16.f32 "
        "{%0,%1,%2,%3}, {%4,%5,%6,%7}, {%8,%9}, {%0,%1,%2,%3};"
        : "+f"(c[0]), "+f"(c[1]), "+f"(c[2]), "+f"(c[3])
        : "r"(a[0]), "r"(a[1]), "r"(a[2]), "r"(a[3]), "r"(b[0]), "r"(b[1]));
}

// ---------------------------------------------------------------------------
// Prepass: fp32 -> fp16 round
// ---------------------------------------------------------------------------
__global__ __launch_bounds__(256) void cvt_round(
    const float* __restrict__ src, __half* __restrict__ dst, int n4)
{
    int i = blockIdx.x * blockDim.x + threadIdx.x;
    if (i >= n4) return;
    float4 v = ((const float4*)src)[i];
    __half2 h[2];
    h[0] = __floats2half2_rn(v.x, v.y);
    h[1] = __floats2half2_rn(v.z, v.w);
    *(uint2*)(dst + (size_t)i * 4) = *(uint2*)h;
}

// ---------------------------------------------------------------------------
// fp16 HMMA GEMM: C = A[M,K] @ W[N,K]^T + bias (opt ReLU, opt fp16 out)
// CTA 128x256, BK=128, 256 thr / 8 warps (2Mx4N), warp tile 64x64, 2-stage.
// Stage (96KB): [A0 16K | A1 16K | B0 32K | B1 32K], each sub-tile 64-k SW128.
// ---------------------------------------------------------------------------
static constexpr int STAGE_B = 98304;
static constexpr int SMEM_BYTES = 2 * STAGE_B;   // 192 KB

template <bool RELU, bool HALF_OUT, int K>
__global__ __launch_bounds__(256, 1) void gemm_mma(
    const __half* __restrict__ A,
    const __half* __restrict__ W,
    const float* __restrict__ bias,
    void* __restrict__ Cv,
    int N)
{
    extern __shared__ __align__(1024) char smem[];
    const uint32_t sbase = smem_to_u32(smem);
    const int tid = threadIdx.x;
    const int lane = tid & 31, w = tid >> 5;
    const int m0 = blockIdx.y * 128, n0 = blockIdx.x * 256;
    const int mw = (w & 1) * 64;
    const int nw = (w >> 1) * 64;

    float acc[4][8][4];
#pragma unroll
    for (int i = 0; i < 4; i++)
#pragma unroll
        for (int j = 0; j < 8; j++)
#pragma unroll
            for (int r = 0; r < 4; r++) acc[i][j][r] = 0.0f;

    const int lrow = tid >> 3;        // 0..31
    const int lsub = tid & 7;         // 0..7
    const __half* Abase = A + (size_t)(m0 + lrow) * K + lsub * 8;
    const __half* Wbase = W + (size_t)(n0 + lrow) * K + lsub * 8;
    const uint32_t ldst = SWZ128((uint32_t)(lrow * 128 + lsub * 16));

    auto issue = [&](int kt, int s) {
        const uint32_t sA = sbase + s * STAGE_B;
        const __half* as = Abase + (size_t)kt * 128;
        const __half* ws = Wbase + (size_t)kt * 128;
#pragma unroll
        for (int t = 0; t < 2; t++) {
#pragma unroll
            for (int p = 0; p < 4; p++)   // A sub-tile t: rows lrow+32p
                CP_ASYNC16(sA + (uint32_t)(t * 16384) + ldst + (uint32_t)(p * 32 * 128),
                           as + t * 64 + (size_t)(p * 32) * K);
#pragma unroll
            for (int p = 0; p < 8; p++)   // B sub-tile t: rows lrow+32p
                CP_ASYNC16(sA + 32768u + (uint32_t)(t * 32768) + ldst + (uint32_t)(p * 32 * 128),
                           ws + t * 64 + (size_t)(p * 32) * K);
        }
        CP_COMMIT();
    };

    auto compute = [&](int s) {
        const uint32_t sA = sbase + s * STAGE_B;
#pragma unroll
        for (int ks = 0; ks < 8; ks++) {
            const uint32_t aA = sA + (uint32_t)((ks >> 2) * 16384);
            const uint32_t aB = sA + 32768u + (uint32_t)((ks >> 2) * 32768);
            const int ksl = ks & 3;
            uint32_t a[4][4], b[4][4];
#pragma unroll
            for (int i = 0; i < 4; i++) {
                const int r = mw + i * 16 + (lane & 15);
                const uint32_t off = (uint32_t)(ksl * 32 + ((lane >> 4) << 4));
                ldsm4(a[i], aA + SWZ128((uint32_t)(r * 128) + off));
            }
#pragma unroll
            for (int jj = 0; jj < 4; jj++) {
                const int r = nw + jj * 16 + ((lane >> 4) << 3) + (lane & 7);
                const uint32_t off = (uint32_t)(ksl * 32 + (((lane >> 3) & 1) << 4));
                ldsm4(b[jj], aB + SWZ128((uint32_t)(r * 128) + off));
            }
#pragma unroll
            for (int i = 0; i < 4; i++)
#pragma unroll
                for (int jj = 0; jj < 4; jj++) {
                    mma16816(acc[i][jj * 2 + 0], a[i], b[jj] + 0);
                    mma16816(acc[i][jj * 2 + 1], a[i], b[jj] + 2);
                }
        }
    };

    constexpr int NT = K / 128;
    issue(0, 0);

#pragma unroll 1
    for (int kt = 0; kt < NT; kt++) {
        const int s = kt & 1;
        CP_WAIT0();
        __syncthreads();
        if (kt + 1 < NT) issue(kt + 1, s ^ 1);
        compute(s);
    }

    // epilogue
#pragma unroll
    for (int i = 0; i < 4; i++) {
        const int mrow = m0 + mw + i * 16 + (lane >> 2);
#pragma unroll
        for (int j = 0; j < 8; j++) {
            const int ncol = n0 + nw + j * 8 + (lane & 3) * 2;
            const float b0 = bias[ncol], b1 = bias[ncol + 1];
            float2 v0 = make_float2(acc[i][j][0] + b0, acc[i][j][1] + b1);
            float2 v1 = make_float2(acc[i][j][2] + b0, acc[i][j][3] + b1);
            if (RELU) {
                v0.x = fmaxf(v0.x, 0.f); v0.y = fmaxf(v0.y, 0.f);
                v1.x = fmaxf(v1.x, 0.f); v1.y = fmaxf(v1.y, 0.f);
            }
            if (HALF_OUT) {
                __half* C = (__half*)Cv;
                __half2 h0 = __floats2half2_rn(v0.x, v0.y);
                __half2 h1 = __floats2half2_rn(v1.x, v1.y);
                *(__half2*)(C + (size_t)mrow * N + ncol) = h0;
                *(__half2*)(C + (size_t)(mrow + 8) * N + ncol) = h1;
            } else {
                float* C = (float*)Cv;
                *(float2*)(C + (size_t)mrow * N + ncol) = v0;
                *(float2*)(C + (size_t)(mrow + 8) * N + ncol) = v1;
            }
        }
    }
}

// ---------------------------------------------------------------------------
// Scan phase 1: local scan over fp16 u; keep only chunk-final state.
// 2 complex dims per thread (uint2 = 4 halves per step).
// ---------------------------------------------------------------------------
__global__ __launch_bounds__(256) void scan_local(const float* __restrict__ plog)
{
    int t = blockIdx.x * blockDim.x + threadIdx.x;   // B*NCH*(DD/2)
    int dh = t % (DD / 2);
    int c  = (t / (DD / 2)) % NCH;
    int b  = t / ((DD / 2) * NCH);
    int d0 = dh * 2;

    float v0 = expf(plog[d0]),      v1 = expf(plog[d0 + 1]);
    float t0 = expf(plog[DD + d0]), t1 = expf(plog[DD + d0 + 1]);
    float r0 = expf(-v0), r1 = expf(-v1);
    float s0, c0s, s1, c1s;
    sincosf(t0, &s0, &c0s);
    sincosf(t1, &s1, &c1s);
    float lre0 = r0 * c0s, lim0 = r0 * s0;
    float lre1 = r1 * c1s, lim1 = r1 * s1;

    size_t base = ((size_t)(b * LSEQ + c * CH)) * (2 * DD) + 2 * d0;  // halves
    float4 s = make_float4(0.f, 0.f, 0.f, 0.f);
#pragma unroll 4
    for (int j = 0; j < CH; j++) {
        uint2 raw = *(const uint2*)(g_uh + base + (size_t)j * (2 * DD));
        float2 u0 = __half22float2(*(__half2*)&raw.x);
        float2 u1 = __half22float2(*(__half2*)&raw.y);
        float a0 = fmaf(lre0, s.x, fmaf(-lim0, s.y, u0.x));
        float a1 = fmaf(lre0, s.y, fmaf( lim0, s.x, u0.y));
        float a2 = fmaf(lre1, s.z, fmaf(-lim1, s.w, u1.x));
        float a3 = fmaf(lre1, s.w, fmaf( lim1, s.z, u1.y));
        s = make_float4(a0, a1, a2, a3);
    }
    *(float4*)(g_last + (size_t)(b * NCH + c) * DD + d0) = s;
}

// ---------------------------------------------------------------------------
// Scan phase 2: carry scan across chunks (2 dims per thread)
// ---------------------------------------------------------------------------
__global__ __launch_bounds__(256) void scan_carry(const float* __restrict__ plog)
{
    int t = blockIdx.x * blockDim.x + threadIdx.x;   // B*(DD/2)
    int dh = t % (DD / 2);
    int b  = t / (DD / 2);
    int d0 = dh * 2;

    float v0 = expf(plog[d0]),      v1 = expf(plog[d0 + 1]);
    float t0 = expf(plog[DD + d0]), t1 = expf(plog[DD + d0 + 1]);
    float Lr0 = expf(-(float)CH * v0), Lr1 = expf(-(float)CH * v1);
    float s0, c0s, s1, c1s;
    sincosf((float)CH * t0, &s0, &c0s);
    sincosf((float)CH * t1, &s1, &c1s);
    float Lre0 = Lr0 * c0s, Lim0 = Lr0 * s0;
    float Lre1 = Lr1 * c1s, Lim1 = Lr1 * s1;

    float4 s = make_float4(0.f, 0.f, 0.f, 0.f);
    for (int k = 0; k < NCH; k++) {
        size_t idx = (size_t)(b * NCH + k) * DD + d0;
        *(float4*)(g_cin + idx) = s;
        float4 last = *(const float4*)(g_last + idx);
        float a0 = fmaf(Lre0, s.x, fmaf(-Lim0, s.y, last.x));
        float a1 = fmaf(Lre0, s.y, fmaf( Lim0, s.x, last.y));
        float a2 = fmaf(Lre1, s.z, fmaf(-Lim1, s.w, last.z));
        float a3 = fmaf(Lre1, s.w, fmaf( Lim1, s.z, last.w));
        s = make_float4(a0, a1, a2, a3);
    }
}

// ---------------------------------------------------------------------------
// Scan phase 3: recompute local scan + carry + gamma, write fp16 [re|im]
// ---------------------------------------------------------------------------
__global__ __launch_bounds__(256) void scan_fix(const float* __restrict__ plog)
{
    int t = blockIdx.x * blockDim.x + threadIdx.x;   // B*NCH*(DD/2)
    int dh = t % (DD / 2);
    int c  = (t / (DD / 2)) % NCH;
    int b  = t / ((DD / 2) * NCH);
    int d0 = dh * 2;

    float v0 = expf(plog[d0]),      v1 = expf(plog[d0 + 1]);
    float t0 = expf(plog[DD + d0]), t1 = expf(plog[DD + d0 + 1]);
    float g0 = expf(plog[2 * DD + d0]), g1 = expf(plog[2 * DD + d0 + 1]);
    float r0 = expf(-v0), r1 = expf(-v1);
    float s0, c0s, s1, c1s;
    sincosf(t0, &s0, &c0s);
    sincosf(t1, &s1, &c1s);
    float lre0 = r0 * c0s, lim0 = r0 * s0;
    float lre1 = r1 * c1s, lim1 = r1 * s1;

    float4 cin = *(const float4*)(g_cin + (size_t)(b * NCH + c) * DD + d0);
    float pre0 = lre0, pim0 = lim0;
    float pre1 = lre1, pim1 = lim1;

    size_t base  = ((size_t)(b * LSEQ + c * CH)) * (2 * DD) + 2 * d0;  // halves
    size_t rbase = ((size_t)(b * LSEQ + c * CH)) * (2 * DD);

    float4 s = make_float4(0.f, 0.f, 0.f, 0.f);
#pragma unroll 4
    for (int j = 0; j < CH; j++) {
        uint2 raw = *(const uint2*)(g_uh + base + (size_t)j * (2 * DD));
        float2 u0 = __half22float2(*(__half2*)&raw.x);
        float2 u1 = __half22float2(*(__half2*)&raw.y);
        float a0 = fmaf(lre0, s.x, fmaf(-lim0, s.y, u0.x));
        float a1 = fmaf(lre0, s.y, fmaf( lim0, s.x, u0.y));
        float a2 = fmaf(lre1, s.z, fmaf(-lim1, s.w, u1.x));
        float a3 = fmaf(lre1, s.w, fmaf( lim1, s.z, u1.y));
        s = make_float4(a0, a1, a2, a3);

        float xre0 = g0 * (s.x + pre0 * cin.x - pim0 * cin.y);
        float xim0 = g0 * (s.y + pre0 * cin.y + pim0 * cin.x);
        float xre1 = g1 * (s.z + pre1 * cin.z - pim1 * cin.w);
        float xim1 = g1 * (s.w + pre1 * cin.w + pim1 * cin.z);
        size_t o = rbase + (size_t)j * (2 * DD) + d0;
        __half2 hre = __floats2half2_rn(xre0, xre1);
        __half2 him = __floats2half2_rn(xim0, xim1);
        *(uint32_t*)(g_xrh + o)      = *(uint32_t*)&hre;
        *(uint32_t*)(g_xrh + o + DD) = *(uint32_t*)&him;

        float n0 = pre0 * lre0 - pim0 * lim0;
        pim0 = pre0 * lim0 + pim0 * lre0; pre0 = n0;
        float n1 = pre1 * lre1 - pim1 * lim1;
        pim1 = pre1 * lim1 + pim1 * lre1; pre1 = n1;
    }
}

// ---------------------------------------------------------------------------
extern "C" void kernel_launch(void* const* d_in, const int* in_sizes, int n_in,
                              void* d_out, int out_size)
{
    const float* inputs = (const float*)d_in[0];
    const float* Wi     = (const float*)d_in[1];
    const float* bi     = (const float*)d_in[2];
    const float* Wo     = (const float*)d_in[3];
    const float* bo     = (const float*)d_in[4];
    const float* plog   = (const float*)d_in[5];

    void *uh, *ih, *wih, *woh, *xh;
    cudaGetSymbolAddress(&uh,  g_uh);
    cudaGetSymbolAddress(&ih,  g_inh);
    cudaGetSymbolAddress(&wih, g_wih);
    cudaGetSymbolAddress(&woh, g_woh);
    cudaGetSymbolAddress(&xh,  g_xrh);

    cudaFuncSetAttribute(gemm_mma<false, true, DD>,
                         cudaFuncAttributeMaxDynamicSharedMemorySize, SMEM_BYTES);
    cudaFuncSetAttribute(gemm_mma<true, false, 2 * DD>,
                         cudaFuncAttributeMaxDynamicSharedMemorySize, SMEM_BYTES);

    // prepasses: fp32 -> fp16
    {
        int n4 = MROWS * DD / 4;
        cvt_round<<<(n4 + 255) / 256, 256>>>(inputs, (__half*)ih, n4);
        n4 = 2 * DD * DD / 4;
        cvt_round<<<(n4 + 255) / 256, 256>>>(Wi, (__half*)wih, n4);
        cvt_round<<<(n4 + 255) / 256, 256>>>(Wo, (__half*)woh, n4);
    }

    // GEMM1: u = inputs @ Wi^T + bi  -> g_uh (fp16)
    gemm_mma<false, true, DD><<<dim3((2 * DD) / 256, MROWS / 128), 256, SMEM_BYTES>>>(
        (const __half*)ih, (const __half*)wih, bi, uh, 2 * DD);

    // Scan
    scan_local<<<(BSZ * NCH * DD / 2) / 256, 256>>>(plog);
    scan_carry<<<(BSZ * DD / 2 + 255) / 256, 256>>>(plog);
    scan_fix<<<(BSZ * NCH * DD / 2) / 256, 256>>>(plog);

    // GEMM2: out = relu(xr @ Wo^T + bo)
    gemm_mma<true, false, 2 * DD><<<dim3(DD / 256, MROWS / 128), 256, SMEM_BYTES>>>(
        (const __half*)xh, (const __half*)woh, bo, d_out, DD);
}